// round 11
// baseline (speedup 1.0000x reference)
#include <cuda_runtime.h>
#include <cuda_fp16.h>
#include <cstdint>
#include <math.h>

// Problem constants
#define BATCH 4
#define SEQ   2048
#define DQ    1024
#define DKV   768
#define NH    4
#define HD    256

// HMMA GEMM tiling (projection GEMMs)
#define TBM 128
#define TBN 128
#define TBK 32
#define NTHREADS 256
#define ROWB  80
#define ATILE (128 * ROWB)
#define STAGEB (2 * ATILE)
#define NSTAGE 4
#define SMEM_TOTAL (NSTAGE * STAGEB)   // 81920 B

// Fused attention tiling (512 threads / 16 warps)
#define ATHREADS 512
#define TQ 64
#define TK 64
#define KVTILES (SEQ / TK)             // 32
#define QROWB 528                      // 256 halfs (512B) + 16B pad
#define PROWB 144                      // 64 halfs (128B) + 16B pad
#define KVTILE (64 * QROWB)            // 33792 B
#define AQ_OFF 0
#define AK_OFF KVTILE                  // K bufs at AK_OFF + buf*2*KVTILE
#define AV_OFF (2 * KVTILE)            // V bufs at AV_OFF + buf*2*KVTILE
#define AP_OFF (5 * KVTILE)            // 168960
#define AM_OFF (AP_OFF + 64 * PROWB)   // 178176  (256 floats)
#define AL_OFF (AM_OFF + 1024)         // 179200  (256 floats)
#define ASMEM  (AL_OFF + 1024)         // 180224 B

#define QK_SCALE 0.09016844005555897f  // log2(e) / 16

// -------- scratch (device globals; no cudaMalloc allowed) -------------------
__device__ __half g_q16 [(long long)BATCH * SEQ * DQ];
__device__ __half g_kv16[(long long)BATCH * SEQ * DKV];
__device__ __half g_wq16[DQ * DQ];
__device__ __half g_wk16[DQ * DKV];
__device__ __half g_wv16[DQ * DKV];
__device__ __half g_wo16[DQ * DQ];
__device__ __half g_qp16 [(long long)BATCH * SEQ * DQ];
__device__ __half g_kp16 [(long long)BATCH * SEQ * DQ];
__device__ __half g_vp16 [(long long)BATCH * SEQ * DQ];
__device__ __half g_ctx16[(long long)BATCH * SEQ * DQ];

// ---------------------------- helpers ---------------------------------------
__device__ __forceinline__ uint32_t smem_u32(const void* p) {
    uint32_t a;
    asm("{ .reg .u64 t; cvta.to.shared.u64 t, %1; cvt.u32.u64 %0, t; }"
        : "=r"(a) : "l"(p));
    return a;
}

__device__ __forceinline__ void cp16(uint32_t dst, const void* src) {
    asm volatile("cp.async.cg.shared.global [%0], [%1], 16;"
                 :: "r"(dst), "l"(src) : "memory");
}

__device__ __forceinline__ void ldsm4(uint32_t addr, uint32_t& r0, uint32_t& r1,
                                      uint32_t& r2, uint32_t& r3) {
    asm volatile("ldmatrix.sync.aligned.m8n8.x4.shared.b16 {%0,%1,%2,%3}, [%4];"
                 : "=r"(r0), "=r"(r1), "=r"(r2), "=r"(r3) : "r"(addr));
}

__device__ __forceinline__ void ldsm4t(uint32_t addr, uint32_t& r0, uint32_t& r1,
                                       uint32_t& r2, uint32_t& r3) {
    asm volatile("ldmatrix.sync.aligned.m8n8.x4.trans.shared.b16 {%0,%1,%2,%3}, [%4];"
                 : "=r"(r0), "=r"(r1), "=r"(r2), "=r"(r3) : "r"(addr));
}

__device__ __forceinline__ void mma16816(float* c, const uint32_t* a,
                                         const uint32_t* b) {
    asm volatile(
        "mma.sync.aligned.m16n8k16.row.col.f32.f16.f16.f32 "
        "{%0,%1,%2,%3}, {%4,%5,%6,%7}, {%8,%9}, {%0,%1,%2,%3};"
        : "+f"(c[0]), "+f"(c[1]), "+f"(c[2]), "+f"(c[3])
        : "r"(a[0]), "r"(a[1]), "r"(a[2]), "r"(a[3]), "r"(b[0]), "r"(b[1]));
}

__device__ __forceinline__ float exp2a(float x) {
    float r;
    asm("ex2.approx.f32 %0, %1;" : "=f"(r) : "f"(x));
    return r;
}

// ---------------------------------------------------------------------------
// fp32 -> fp16 conversion with optional scale (n multiple of 4)
// ---------------------------------------------------------------------------
__global__ void f2h_kernel(const float4* __restrict__ in, uint2* __restrict__ out,
                           long long n4, float mul)
{
    long long i = (long long)blockIdx.x * blockDim.x + threadIdx.x;
    if (i >= n4) return;
    float4 v = in[i];
    __half2 h0 = __floats2half2_rn(v.x * mul, v.y * mul);
    __half2 h1 = __floats2half2_rn(v.z * mul, v.w * mul);
    uint2 u;
    u.x = *reinterpret_cast<uint32_t*>(&h0);
    u.y = *reinterpret_cast<uint32_t*>(&h1);
    out[i] = u;
}

// ---------------------------------------------------------------------------
// HMMA fp16 NT GEMM with cp.async 4-stage pipeline, 2 CTAs/SM. (unchanged)
// outMode: 0 = fp32 C (+bias), 1 = fp16 C
// ---------------------------------------------------------------------------
__global__ __launch_bounds__(NTHREADS, 2)
void gemm_hmma16(const __half* __restrict__ A, const __half* __restrict__ B,
                 const float* __restrict__ bias, void* __restrict__ Cv,
                 int K, int lda, int ldb, int ldc,
                 float alpha, int outMode)
{
    extern __shared__ __align__(16) char sm[];
    const uint32_t smbase = smem_u32(sm);

    const int tid = threadIdx.x;
    const int lane = tid & 31, wid = tid >> 5;
    const int wm = wid & 3, wn = wid >> 2;

    const int bm = blockIdx.y * TBM, bn = blockIdx.x * TBN;

    const int srow = tid >> 2;
    const int sc   = tid & 3;
    const __half* gA = A + (long long)(bm + srow) * lda + sc * 8;
    const __half* gB = B + (long long)(bn + srow) * ldb + sc * 8;
    const uint32_t stsA = smbase + (uint32_t)srow * ROWB + sc * 16;
    const uint32_t stsB = stsA + ATILE;
    const long long a64 = 64LL * lda, b64 = 64LL * ldb;

    uint32_t a_addr[2], b_addr[4];
    {
        const int ar = wm * 32 + (lane & 15);
        const int ac = lane >> 4;
        #pragma unroll
        for (int t = 0; t < 2; ++t)
            a_addr[t] = smbase + (uint32_t)(ar + t * 16) * ROWB + ac * 16;
        const int br = wn * 64 + (lane & 7) + ((lane >> 4) << 3);
        const int bc = (lane >> 3) & 1;
        #pragma unroll
        for (int u = 0; u < 4; ++u)
            b_addr[u] = smbase + ATILE + (uint32_t)(br + u * 16) * ROWB + bc * 16;
    }

    float c[2][8][4];
    #pragma unroll
    for (int t = 0; t < 2; ++t)
        #pragma unroll
        for (int j = 0; j < 8; ++j)
            #pragma unroll
            for (int r = 0; r < 4; ++r)
                c[t][j][r] = 0.0f;

    const int KT = K / TBK;

    #pragma unroll
    for (int p = 0; p < NSTAGE - 1; ++p) {
        const uint32_t so = (uint32_t)p * STAGEB;
        const int kp = p * TBK;
        cp16(stsA + so, gA + kp);
        cp16(stsA + so + 64 * ROWB, gA + kp + a64);
        cp16(stsB + so, gB + kp);
        cp16(stsB + so + 64 * ROWB, gB + kp + b64);
        asm volatile("cp.async.commit_group;" ::: "memory");
    }

    for (int kt = 0; kt < KT; ++kt) {
        asm volatile("cp.async.wait_group %0;" :: "n"(NSTAGE - 2) : "memory");
        __syncthreads();

        const int ns = kt + NSTAGE - 1;
        if (ns < KT) {
            const uint32_t so = (uint32_t)(ns & (NSTAGE - 1)) * STAGEB;
            const int kp = ns * TBK;
            cp16(stsA + so, gA + kp);
            cp16(stsA + so + 64 * ROWB, gA + kp + a64);
            cp16(stsB + so, gB + kp);
            cp16(stsB + so + 64 * ROWB, gB + kp + b64);
        }
        asm volatile("cp.async.commit_group;" ::: "memory");

        const uint32_t soff = (uint32_t)(kt & (NSTAGE - 1)) * STAGEB;
        #pragma unroll
        for (int s = 0; s < 2; ++s) {
            uint32_t af[2][4], bf[4][4];
            #pragma unroll
            for (int t = 0; t < 2; ++t)
                ldsm4(a_addr[t] + soff + s * 32,
                      af[t][0], af[t][1], af[t][2], af[t][3]);
            #pragma unroll
            for (int u = 0; u < 4; ++u)
                ldsm4(b_addr[u] + soff + s * 32,
                      bf[u][0], bf[u][1], bf[u][2], bf[u][3]);
            #pragma unroll
            for (int t = 0; t < 2; ++t)
                #pragma unroll
                for (int j = 0; j < 8; ++j)
                    mma16816(c[t][j], af[t], &bf[j >> 1][(j & 1) * 2]);
        }
    }

    #pragma unroll
    for (int t = 0; t < 2; ++t) {
        const int m0 = bm + wm * 32 + t * 16 + (lane >> 2);
        #pragma unroll
        for (int j = 0; j < 8; ++j) {
            const int n0 = bn + wn * 64 + j * 8 + (lane & 3) * 2;
            float v0 = c[t][j][0] * alpha;
            float v1 = c[t][j][1] * alpha;
            float v2 = c[t][j][2] * alpha;
            float v3 = c[t][j][3] * alpha;
            if (outMode == 0) {
                float* C = (float*)Cv;
                if (bias) {
                    const float b0 = bias[n0], b1 = bias[n0 + 1];
                    v0 += b0; v1 += b1; v2 += b0; v3 += b1;
                }
                *(float2*)(C + (long long)m0 * ldc + n0) = make_float2(v0, v1);
                *(float2*)(C + (long long)(m0 + 8) * ldc + n0) = make_float2(v2, v3);
            } else {
                __half* C = (__half*)Cv;
                __half2 lo = __floats2half2_rn(v0, v1);
                __half2 hi = __floats2half2_rn(v2, v3);
                *(__half2*)(C + (long long)m0 * ldc + n0) = lo;
                *(__half2*)(C + (long long)(m0 + 8) * ldc + n0) = hi;
            }
        }
    }
}

// ---------------------------------------------------------------------------
// Fused flash attention, 512 threads / 16 warps.
// S-phase warp grid: 4 q-groups (16 rows) x 4 key-groups (16 keys).
// PV-phase warp grid: 4 q-groups x 4 hd-groups (64 cols, oacc 32 regs).
// ---------------------------------------------------------------------------
__global__ __launch_bounds__(ATHREADS, 1)
void attn_fused(const __half* __restrict__ Qp, const __half* __restrict__ Kp,
                const __half* __restrict__ Vp, __half* __restrict__ Ctx)
{
    extern __shared__ __align__(16) char sm[];
    const uint32_t sb = smem_u32(sm);

    const int tid = threadIdx.x;
    const int lane = tid & 31, wid = tid >> 5;
    const int wq = wid & 3;        // q row group (16 rows)
    const int wg = wid >> 2;       // S: key group (16 keys); PV: hd group (64 cols)
    const int qt = blockIdx.x, h = blockIdx.y, b = blockIdx.z;

    const long long qbase  = ((long long)b * SEQ + qt * TQ) * DQ + h * HD;
    const long long kvbase = ((long long)b * SEQ) * DQ + h * HD;

    // ---- prologue loads: Q + KV tiles 0,1 (8 threads/row, 4 chunks each) ---
    {
        const int row = tid >> 3, c0 = tid & 7;
        const __half* gq = Qp + qbase + (long long)row * DQ;
        const __half* gk = Kp + kvbase + (long long)row * DQ;
        const __half* gv = Vp + kvbase + (long long)row * DQ;
        const uint32_t so = sb + (uint32_t)row * QROWB;
        #pragma unroll
        for (int j = 0; j < 4; ++j) {
            const int c = c0 + j * 8;
            cp16(so + AQ_OFF + c * 16, gq + c * 8);
        }
        #pragma unroll
        for (int j = 0; j < 4; ++j) {
            const int c = c0 + j * 8;
            cp16(so + AK_OFF + c * 16, gk + c * 8);
            cp16(so + AV_OFF + c * 16, gv + c * 8);
        }
        asm volatile("cp.async.commit_group;" ::: "memory");
        #pragma unroll
        for (int j = 0; j < 4; ++j) {
            const int c = c0 + j * 8;
            cp16(so + AK_OFF + 2 * KVTILE + c * 16, gk + 64LL * DQ + c * 8);
            cp16(so + AV_OFF + 2 * KVTILE + c * 16, gv + 64LL * DQ + c * 8);
        }
        asm volatile("cp.async.commit_group;" ::: "memory");
    }

    // ---- ldmatrix / store addresses -----------------------------------------
    // Q: A-operand map
    const uint32_t qa = sb + AQ_OFF + (uint32_t)(wq * 16 + (lane & 15)) * QROWB
                        + ((lane >> 4) << 4);
    // K: B-operand map, 16 keys per group
    const uint32_t ka_r = (uint32_t)(wg * 16 + (lane & 7) + ((lane >> 4) << 3)) * QROWB
                          + (((lane >> 3) & 1) << 4);
    // P: A-operand map
    const uint32_t pa = sb + AP_OFF + (uint32_t)(wq * 16 + (lane & 15)) * PROWB
                        + ((lane >> 4) << 4);
    // V (trans): rows = keys, hd group at wg*64 halfs (128B)
    const uint32_t va_r = (uint32_t)(lane & 15) * QROWB + wg * 128
                          + ((lane >> 4) << 4);
    const int row_i = wq * 16 + (lane >> 2);             // row r0 (0..63)
    const uint32_t pst = sb + AP_OFF + (uint32_t)row_i * PROWB
                         + (uint32_t)(wg * 16 + (lane & 3) * 2) * 2;
    float* mp = (float*)(sm + AM_OFF);
    float* lp = (float*)(sm + AL_OFF);

    float oacc[8][4];
    #pragma unroll
    for (int j = 0; j < 8; ++j)
        #pragma unroll
        for (int r = 0; r < 4; ++r)
            oacc[j][r] = 0.0f;
    float mrun0 = -1e30f, mrun1 = -1e30f, lrun0 = 0.0f, lrun1 = 0.0f;

    for (int t = 0; t < KVTILES; ++t) {
        const int buf = t & 1;
        asm volatile("cp.async.wait_group 1;" ::: "memory");
        __syncthreads();

        const uint32_t kb = sb + AK_OFF + (uint32_t)buf * 2 * KVTILE;
        const uint32_t vb = sb + AV_OFF + (uint32_t)buf * 2 * KVTILE;

        // ---- S = Q @ K^T (16x16 per warp, hd=256 -> 16 ksteps) -------------
        float sfr[2][4];
        #pragma unroll
        for (int j = 0; j < 2; ++j)
            #pragma unroll
            for (int r = 0; r < 4; ++r)
                sfr[j][r] = 0.0f;

        #pragma unroll
        for (int s = 0; s < 16; ++s) {
            uint32_t aq[4], bk[4];
            ldsm4(qa + s * 32, aq[0], aq[1], aq[2], aq[3]);
            ldsm4(kb + ka_r + s * 32, bk[0], bk[1], bk[2], bk[3]);
            mma16816(sfr[0], aq, &bk[0]);
            mma16816(sfr[1], aq, &bk[2]);
        }

        // ---- row max, combine across quad + 4 key groups -------------------
        float mr0 = fmaxf(fmaxf(sfr[0][0], sfr[0][1]), fmaxf(sfr[1][0], sfr[1][1]));
        float mr1 = fmaxf(fmaxf(sfr[0][2], sfr[0][3]), fmaxf(sfr[1][2], sfr[1][3]));
        #pragma unroll
        for (int o = 1; o <= 2; o <<= 1) {
            mr0 = fmaxf(mr0, __shfl_xor_sync(0xffffffffu, mr0, o));
            mr1 = fmaxf(mr1, __shfl_xor_sync(0xffffffffu, mr1, o));
        }
        if ((lane & 3) == 0) {
            mp[wg * 64 + row_i] = mr0;
            mp[wg * 64 + row_i + 8] = mr1;
        }
        __syncthreads();   // sync1: m parts visible

        const float mn0 = fmaxf(fmaxf(fmaxf(mp[row_i], mp[64 + row_i]),
                                      fmaxf(mp[128 + row_i], mp[192 + row_i])), mrun0);
        const float mn1 = fmaxf(fmaxf(fmaxf(mp[row_i + 8], mp[64 + row_i + 8]),
                                      fmaxf(mp[128 + row_i + 8], mp[192 + row_i + 8])), mrun1);
        const float al0 = exp2a(mrun0 - mn0);
        const float al1 = exp2a(mrun1 - mn1);
        mrun0 = mn0; mrun1 = mn1;

        // ---- p = exp2(s - m), partial sums, store P fp16 --------------------
        float sum0 = 0.0f, sum1 = 0.0f;
        #pragma unroll
        for (int j = 0; j < 2; ++j) {
            const float p0 = exp2a(sfr[j][0] - mn0);
            const float p1 = exp2a(sfr[j][1] - mn0);
            const float p2 = exp2a(sfr[j][2] - mn1);
            const float p3 = exp2a(sfr[j][3] - mn1);
            sum0 += p0 + p1;
            sum1 += p2 + p3;
            __half2 h01 = __floats2half2_rn(p0, p1);
            __half2 h23 = __floats2half2_rn(p2, p3);
            *(__half2*)(sm + (pst - sb) + j * 16) = h01;
            *(__half2*)(sm + (pst - sb) + 8 * PROWB + j * 16) = h23;
        }
        #pragma unroll
        for (int o = 1; o <= 2; o <<= 1) {
            sum0 += __shfl_xor_sync(0xffffffffu, sum0, o);
            sum1 += __shfl_xor_sync(0xffffffffu, sum1, o);
        }
        if ((lane & 3) == 0) {
            lp[wg * 64 + row_i] = sum0;
            lp[wg * 64 + row_i + 8] = sum1;
        }

        // ---- rescale O by alpha ---------------------------------------------
        #pragma unroll
        for (int j = 0; j < 8; ++j) {
            oacc[j][0] *= al0; oacc[j][1] *= al0;
            oacc[j][2] *= al1; oacc[j][3] *= al1;
        }
        __syncthreads();   // sync2: P + l parts visible

        lrun0 = lrun0 * al0 + (lp[row_i] + lp[64 + row_i])
                            + (lp[128 + row_i] + lp[192 + row_i]);
        lrun1 = lrun1 * al1 + (lp[row_i + 8] + lp[64 + row_i + 8])
                            + (lp[128 + row_i + 8] + lp[192 + row_i + 8]);

        // ---- O += P @ V (16 rows x 64 hd per warp, k=64 keys) ---------------
        #pragma unroll
        for (int s4 = 0; s4 < 4; ++s4) {
            uint32_t ap[4];
            ldsm4(pa + s4 * 32, ap[0], ap[1], ap[2], ap[3]);
            #pragma unroll
            for (int g = 0; g < 4; ++g) {
                uint32_t bv[4];
                ldsm4t(vb + va_r + (uint32_t)s4 * 16 * QROWB + g * 32,
                       bv[0], bv[1], bv[2], bv[3]);
                mma16816(oacc[2 * g], ap, &bv[0]);
                mma16816(oacc[2 * g + 1], ap, &bv[2]);
            }
        }
        __syncthreads();   // sync3: buffers free for prefetch / P rewrite

        // ---- prefetch tile t+2 into buf --------------------------------------
        if (t + 2 < KVTILES) {
            const int row = tid >> 3, c0 = tid & 7;
            const long long off = kvbase + ((long long)(t + 2) * TK + row) * DQ;
            const __half* gk = Kp + off;
            const __half* gv = Vp + off;
            const uint32_t so = sb + (uint32_t)row * QROWB + (uint32_t)buf * 2 * KVTILE;
            #pragma unroll
            for (int j = 0; j < 4; ++j) {
                const int c = c0 + j * 8;
                cp16(so + AK_OFF + c * 16, gk + c * 8);
                cp16(so + AV_OFF + c * 16, gv + c * 8);
            }
        }
        asm volatile("cp.async.commit_group;" ::: "memory");
    }

    // ---- epilogue: O /= l, store fp16 ---------------------------------------
    const float inv0 = 1.0f / lrun0;
    const float inv1 = 1.0f / lrun1;
    const long long m0 = (long long)b * SEQ + qt * TQ + row_i;
    __half* crow0 = Ctx + m0 * DQ + h * HD + wg * 64 + (lane & 3) * 2;
    __half* crow1 = crow0 + 8LL * DQ;
    #pragma unroll
    for (int j = 0; j < 8; ++j) {
        __half2 lo = __floats2half2_rn(oacc[j][0] * inv0, oacc[j][1] * inv0);
        __half2 hi = __floats2half2_rn(oacc[j][2] * inv1, oacc[j][3] * inv1);
        *(__half2*)(crow0 + j * 8) = lo;
        *(__half2*)(crow1 + j * 8) = hi;
    }
}

// ---------------------------------------------------------------------------
extern "C" void kernel_launch(void* const* d_in, const int* in_sizes, int n_in,
                              void* d_out, int out_size)
{
    const float* q  = (const float*)d_in[0];
    const float* kv = (const float*)d_in[1];
    const float* Wq = (const float*)d_in[2];
    const float* Wk = (const float*)d_in[3];
    const float* Wv = (const float*)d_in[4];
    const float* Wo = (const float*)d_in[5];
    const float* bo = (const float*)d_in[6];
    float* out = (float*)d_out;

    __half *q16, *kv16, *wq16, *wk16, *wv16, *wo16;
    __half *qp16, *kp16, *vp16, *ctx16;
    cudaGetSymbolAddress((void**)&q16,  g_q16);
    cudaGetSymbolAddress((void**)&kv16, g_kv16);
    cudaGetSymbolAddress((void**)&wq16, g_wq16);
    cudaGetSymbolAddress((void**)&wk16, g_wk16);
    cudaGetSymbolAddress((void**)&wv16, g_wv16);
    cudaGetSymbolAddress((void**)&wo16, g_wo16);
    cudaGetSymbolAddress((void**)&qp16,  g_qp16);
    cudaGetSymbolAddress((void**)&kp16,  g_kp16);
    cudaGetSymbolAddress((void**)&vp16,  g_vp16);
    cudaGetSymbolAddress((void**)&ctx16, g_ctx16);

    cudaFuncSetAttribute(gemm_hmma16, cudaFuncAttributeMaxDynamicSharedMemorySize,
                         SMEM_TOTAL);
    cudaFuncSetAttribute(attn_fused, cudaFuncAttributeMaxDynamicSharedMemorySize,
                         ASMEM);

    const int MT = BATCH * SEQ;        // 8192

    // 0) fp32 -> fp16 conversions (Wq pre-scaled by log2(e)/16 for base-2 softmax)
    {
        struct { const float* src; __half* dst; long long n; float mul; } cv[6] = {
            { q,  q16,  (long long)BATCH * SEQ * DQ,  1.0f },
            { kv, kv16, (long long)BATCH * SEQ * DKV, 1.0f },
            { Wq, wq16, (long long)DQ * DQ,  QK_SCALE },
            { Wk, wk16, (long long)DQ * DKV, 1.0f },
            { Wv, wv16, (long long)DQ * DKV, 1.0f },
            { Wo, wo16, (long long)DQ * DQ,  1.0f },
        };
        for (int i = 0; i < 6; ++i) {
            long long n4 = cv[i].n / 4;
            int g = (int)((n4 + 255) / 256);
            f2h_kernel<<<g, 256>>>((const float4*)cv[i].src, (uint2*)cv[i].dst,
                                   n4, cv[i].mul);
        }
    }

    // 1) qp16 = q16 @ (Wq*scale)^T
    gemm_hmma16<<<dim3(DQ / TBN, MT / TBM, 1), NTHREADS, SMEM_TOTAL>>>(
        q16, wq16, nullptr, qp16, DQ, DQ, DQ, DQ, 1.0f, 1);

    // 2) kp16 = kv16 @ Wk^T
    gemm_hmma16<<<dim3(DQ / TBN, MT / TBM, 1), NTHREADS, SMEM_TOTAL>>>(
        kv16, wk16, nullptr, kp16, DKV, DKV, DKV, DQ, 1.0f, 1);

    // 3) vp16 = kv16 @ Wv^T
    gemm_hmma16<<<dim3(DQ / TBN, MT / TBM, 1), NTHREADS, SMEM_TOTAL>>>(
        kv16, wv16, nullptr, vp16, DKV, DKV, DKV, DQ, 1.0f, 1);

    // 4) fused attention: ctx16 = softmax(qp kp^T) vp
    attn_fused<<<dim3(SEQ / TQ, NH, BATCH), dim3(ATHREADS), ASMEM>>>(
        qp16, kp16, vp16, ctx16);

    // 5) out = ctx16 @ Wo^T + bo  (fp32 out)
    gemm_hmma16<<<dim3(DQ / TBN, MT / TBM, 1), NTHREADS, SMEM_TOTAL>>>(
        ctx16, wo16, bo, out, DQ, DQ, DQ, DQ, 1.0f, 0);
}

// round 12
// speedup vs baseline: 1.2004x; 1.2004x over previous
#include <cuda_runtime.h>
#include <cuda_fp16.h>
#include <cstdint>
#include <math.h>

// Problem constants
#define BATCH 4
#define SEQ   2048
#define DQ    1024
#define DKV   768
#define NH    4
#define HD    256

// HMMA GEMM tiling
#define TBM 128
#define TBN 128
#define TBK 32
#define NTHREADS 256
#define ROWB  80
#define ATILE (128 * ROWB)
#define STAGEB (2 * ATILE)
#define NSTAGE 4
#define SMEM_TOTAL (NSTAGE * STAGEB)   // 81920 B

#define QK_SCALE 0.09016844005555897f  // log2(e) / 16

// -------- scratch (device globals; no cudaMalloc allowed) -------------------
__device__ __half g_q16 [(long long)BATCH * SEQ * DQ];
__device__ __half g_kv16[(long long)BATCH * SEQ * DKV];
__device__ __half g_wq16[DQ * DQ];
__device__ __half g_wk16[DQ * DKV];
__device__ __half g_wv16[DQ * DKV];
__device__ __half g_wo16[DQ * DQ];
__device__ __half g_qp16 [(long long)BATCH * SEQ * DQ];
__device__ __half g_kp16 [(long long)BATCH * SEQ * DQ];
__device__ __half g_vpT16[(long long)BATCH * DQ * SEQ];   // V transposed
__device__ __half g_ctx16[(long long)BATCH * SEQ * DQ];
__device__ __half g_sc16 [(long long)BATCH * NH * SEQ * SEQ]; // fp16 scores (128MB)
__device__ __half g_p16  [(long long)BATCH * NH * SEQ * SEQ]; // fp16 probs  (128MB)

// ---------------------------- helpers ---------------------------------------
__device__ __forceinline__ uint32_t smem_u32(const void* p) {
    uint32_t a;
    asm("{ .reg .u64 t; cvta.to.shared.u64 t, %1; cvt.u32.u64 %0, t; }"
        : "=r"(a) : "l"(p));
    return a;
}

__device__ __forceinline__ void cp16(uint32_t dst, const void* src) {
    asm volatile("cp.async.cg.shared.global [%0], [%1], 16;"
                 :: "r"(dst), "l"(src) : "memory");
}

__device__ __forceinline__ void ldsm4(uint32_t addr, uint32_t& r0, uint32_t& r1,
                                      uint32_t& r2, uint32_t& r3) {
    asm volatile("ldmatrix.sync.aligned.m8n8.x4.shared.b16 {%0,%1,%2,%3}, [%4];"
                 : "=r"(r0), "=r"(r1), "=r"(r2), "=r"(r3) : "r"(addr));
}

__device__ __forceinline__ void mma16816(float* c, const uint32_t* a,
                                         const uint32_t* b) {
    asm volatile(
        "mma.sync.aligned.m16n8k16.row.col.f32.f16.f16.f32 "
        "{%0,%1,%2,%3}, {%4,%5,%6,%7}, {%8,%9}, {%0,%1,%2,%3};"
        : "+f"(c[0]), "+f"(c[1]), "+f"(c[2]), "+f"(c[3])
        : "r"(a[0]), "r"(a[1]), "r"(a[2]), "r"(a[3]), "r"(b[0]), "r"(b[1]));
}

__device__ __forceinline__ float exp2a(float x) {
    float r;
    asm("ex2.approx.f32 %0, %1;" : "=f"(r) : "f"(x));
    return r;
}

__device__ __forceinline__ uint2 cvt8(float4 a, float4 b, float mul) {
    __half2 h0 = __floats2half2_rn(a.x * mul, a.y * mul);
    __half2 h1 = __floats2half2_rn(a.z * mul, a.w * mul);
    uint2 u;
    u.x = *reinterpret_cast<uint32_t*>(&h0);
    u.y = *reinterpret_cast<uint32_t*>(&h1);
    (void)b;
    return u;
}

// ---------------------------------------------------------------------------
// Segmented fp32 -> fp16 conversions (2 segments / 4 segments per launch)
// ---------------------------------------------------------------------------
__global__ void conv2_kernel(const float4* __restrict__ s0, uint2* __restrict__ d0,
                             long long n0, float m0,
                             const float4* __restrict__ s1, uint2* __restrict__ d1,
                             long long n1, float m1)
{
    long long i = (long long)blockIdx.x * blockDim.x + threadIdx.x;
    const float4* s; uint2* d; float m;
    if (i < n0) { s = s0 + i; d = d0 + i; m = m0; }
    else {
        i -= n0;
        if (i >= n1) return;
        s = s1 + i; d = d1 + i; m = m1;
    }
    float4 v = *s;
    __half2 h0 = __floats2half2_rn(v.x * m, v.y * m);
    __half2 h1 = __floats2half2_rn(v.z * m, v.w * m);
    uint2 u;
    u.x = *reinterpret_cast<uint32_t*>(&h0);
    u.y = *reinterpret_cast<uint32_t*>(&h1);
    *d = u;
}

__global__ void conv4_kernel(const float4* __restrict__ s0, uint2* __restrict__ d0,
                             long long n0, float m0,
                             const float4* __restrict__ s1, uint2* __restrict__ d1,
                             long long n1, float m1,
                             const float4* __restrict__ s2, uint2* __restrict__ d2,
                             long long n2, float m2,
                             const float4* __restrict__ s3, uint2* __restrict__ d3,
                             long long n3, float m3)
{
    long long i = (long long)blockIdx.x * blockDim.x + threadIdx.x;
    const float4* s; uint2* d; float m;
    if (i < n0) { s = s0 + i; d = d0 + i; m = m0; }
    else if (i < n0 + n1) { i -= n0; s = s1 + i; d = d1 + i; m = m1; }
    else if (i < n0 + n1 + n2) { i -= n0 + n1; s = s2 + i; d = d2 + i; m = m2; }
    else {
        i -= n0 + n1 + n2;
        if (i >= n3) return;
        s = s3 + i; d = d3 + i; m = m3;
    }
    float4 v = *s;
    __half2 h0 = __floats2half2_rn(v.x * m, v.y * m);
    __half2 h1 = __floats2half2_rn(v.z * m, v.w * m);
    uint2 u;
    u.x = *reinterpret_cast<uint32_t*>(&h0);
    u.y = *reinterpret_cast<uint32_t*>(&h1);
    *d = u;
}

// ---------------------------------------------------------------------------
// HMMA fp16 NT GEMM with cp.async 4-stage pipeline, 2 CTAs/SM (round-7 kernel).
//   C[m,n] = alpha * sum_k A[m,k]*B[n,k]  (+ bias[n] if mode 0)
// Batched over blockIdx.z with (batch, head) strides.
// outMode: 0 = fp32 C (+bias), 1 = fp16 C, 2 = fp16 C transposed
//          (C[(b*DQ + n)*SEQ + l], b=m>>11, l=m&2047).
// ---------------------------------------------------------------------------
__global__ __launch_bounds__(NTHREADS, 2)
void gemm_hmma16(const __half* __restrict__ A, const __half* __restrict__ B,
                 const float* __restrict__ bias, void* __restrict__ Cv,
                 int K, int lda, int ldb, int ldc, int nh,
                 long long sAb, long long sAh, long long sBb, long long sBh,
                 long long sCb, long long sCh, float alpha, int outMode)
{
    extern __shared__ __align__(16) char sm[];
    const uint32_t smbase = smem_u32(sm);

    const int tid = threadIdx.x;
    const int lane = tid & 31, wid = tid >> 5;
    const int wm = wid & 3, wn = wid >> 2;   // warp grid: 4 (m) x 2 (n)

    const int z = blockIdx.z, bz = z / nh, hz = z - bz * nh;
    A += bz * sAb + hz * sAh;
    B += bz * sBb + hz * sBh;
    const int bm = blockIdx.y * TBM, bn = blockIdx.x * TBN;

    const int srow = tid >> 2;
    const int sc   = tid & 3;
    const __half* gA = A + (long long)(bm + srow) * lda + sc * 8;
    const __half* gB = B + (long long)(bn + srow) * ldb + sc * 8;
    const uint32_t stsA = smbase + (uint32_t)srow * ROWB + sc * 16;
    const uint32_t stsB = stsA + ATILE;
    const long long a64 = 64LL * lda, b64 = 64LL * ldb;

    uint32_t a_addr[2], b_addr[4];
    {
        const int ar = wm * 32 + (lane & 15);
        const int ac = lane >> 4;
        #pragma unroll
        for (int t = 0; t < 2; ++t)
            a_addr[t] = smbase + (uint32_t)(ar + t * 16) * ROWB + ac * 16;
        const int br = wn * 64 + (lane & 7) + ((lane >> 4) << 3);
        const int bc = (lane >> 3) & 1;
        #pragma unroll
        for (int u = 0; u < 4; ++u)
            b_addr[u] = smbase + ATILE + (uint32_t)(br + u * 16) * ROWB + bc * 16;
    }

    float c[2][8][4];
    #pragma unroll
    for (int t = 0; t < 2; ++t)
        #pragma unroll
        for (int j = 0; j < 8; ++j)
            #pragma unroll
            for (int r = 0; r < 4; ++r)
                c[t][j][r] = 0.0f;

    const int KT = K / TBK;

    #pragma unroll
    for (int p = 0; p < NSTAGE - 1; ++p) {
        const uint32_t so = (uint32_t)p * STAGEB;
        const int kp = p * TBK;
        cp16(stsA + so, gA + kp);
        cp16(stsA + so + 64 * ROWB, gA + kp + a64);
        cp16(stsB + so, gB + kp);
        cp16(stsB + so + 64 * ROWB, gB + kp + b64);
        asm volatile("cp.async.commit_group;" ::: "memory");
    }

    for (int kt = 0; kt < KT; ++kt) {
        asm volatile("cp.async.wait_group %0;" :: "n"(NSTAGE - 2) : "memory");
        __syncthreads();

        const int ns = kt + NSTAGE - 1;
        if (ns < KT) {
            const uint32_t so = (uint32_t)(ns & (NSTAGE - 1)) * STAGEB;
            const int kp = ns * TBK;
            cp16(stsA + so, gA + kp);
            cp16(stsA + so + 64 * ROWB, gA + kp + a64);
            cp16(stsB + so, gB + kp);
            cp16(stsB + so + 64 * ROWB, gB + kp + b64);
        }
        asm volatile("cp.async.commit_group;" ::: "memory");

        const uint32_t soff = (uint32_t)(kt & (NSTAGE - 1)) * STAGEB;
        #pragma unroll
        for (int s = 0; s < 2; ++s) {
            uint32_t af[2][4], bf[4][4];
            #pragma unroll
            for (int t = 0; t < 2; ++t)
                ldsm4(a_addr[t] + soff + s * 32,
                      af[t][0], af[t][1], af[t][2], af[t][3]);
            #pragma unroll
            for (int u = 0; u < 4; ++u)
                ldsm4(b_addr[u] + soff + s * 32,
                      bf[u][0], bf[u][1], bf[u][2], bf[u][3]);
            #pragma unroll
            for (int t = 0; t < 2; ++t)
                #pragma unroll
                for (int j = 0; j < 8; ++j)
                    mma16816(c[t][j], af[t], &bf[j >> 1][(j & 1) * 2]);
        }
    }

    #pragma unroll
    for (int t = 0; t < 2; ++t) {
        const int m0 = bm + wm * 32 + t * 16 + (lane >> 2);
        #pragma unroll
        for (int j = 0; j < 8; ++j) {
            const int n0 = bn + wn * 64 + j * 8 + (lane & 3) * 2;
            float v0 = c[t][j][0] * alpha;
            float v1 = c[t][j][1] * alpha;
            float v2 = c[t][j][2] * alpha;
            float v3 = c[t][j][3] * alpha;
            if (outMode == 0) {
                float* C = (float*)Cv + bz * sCb + hz * sCh;
                if (bias) {
                    const float b0 = bias[n0], b1 = bias[n0 + 1];
                    v0 += b0; v1 += b1; v2 += b0; v3 += b1;
                }
                *(float2*)(C + (long long)m0 * ldc + n0) = make_float2(v0, v1);
                *(float2*)(C + (long long)(m0 + 8) * ldc + n0) = make_float2(v2, v3);
            } else if (outMode == 1) {
                __half* C = (__half*)Cv + bz * sCb + hz * sCh;
                __half2 lo = __floats2half2_rn(v0, v1);
                __half2 hi = __floats2half2_rn(v2, v3);
                *(__half2*)(C + (long long)m0 * ldc + n0) = lo;
                *(__half2*)(C + (long long)(m0 + 8) * ldc + n0) = hi;
            } else {
                __half* C = (__half*)Cv;
                const int b0i = m0 >> 11, l0 = m0 & 2047;
                const int m1 = m0 + 8;
                const int b1i = m1 >> 11, l1 = m1 & 2047;
                C[(long long)(b0i * DQ + n0)     * SEQ + l0] = __float2half_rn(v0);
                C[(long long)(b0i * DQ + n0 + 1) * SEQ + l0] = __float2half_rn(v1);
                C[(long long)(b1i * DQ + n0)     * SEQ + l1] = __float2half_rn(v2);
                C[(long long)(b1i * DQ + n0 + 1) * SEQ + l1] = __float2half_rn(v3);
            }
        }
    }
}

// ---------------------------------------------------------------------------
// Row softmax in base-2: read fp16 scores (pre-scaled by log2e/16 in Wq),
// write fp16 probs. ncols=2048, 256 threads, 8 halfs/thread (16B vectors).
// ---------------------------------------------------------------------------
__device__ __forceinline__ float warp_max(float v) {
    #pragma unroll
    for (int o = 16; o > 0; o >>= 1) v = fmaxf(v, __shfl_xor_sync(0xffffffffu, v, o));
    return v;
}
__device__ __forceinline__ float warp_sum(float v) {
    #pragma unroll
    for (int o = 16; o > 0; o >>= 1) v += __shfl_xor_sync(0xffffffffu, v, o);
    return v;
}

__global__ __launch_bounds__(256)
void softmax16_kernel(const __half* __restrict__ S, __half* __restrict__ P)
{
    const long long rowoff = (long long)blockIdx.x * SEQ;
    const int tid = threadIdx.x;
    const int wid = tid >> 5, lid = tid & 31;
    __shared__ float red[8];

    uint4 raw = *(const uint4*)(S + rowoff + tid * 8);
    const __half2* hp = (const __half2*)&raw;
    float v[8];
    #pragma unroll
    for (int i = 0; i < 4; ++i) {
        float2 f = __half22float2(hp[i]);
        v[2 * i] = f.x;
        v[2 * i + 1] = f.y;
    }

    float m = -1e30f;
    #pragma unroll
    for (int i = 0; i < 8; ++i) m = fmaxf(m, v[i]);
    m = warp_max(m);
    if (lid == 0) red[wid] = m;
    __syncthreads();
    if (wid == 0) {
        float t = (lid < 8) ? red[lid] : -1e30f;
        t = warp_max(t);
        if (lid == 0) red[0] = t;
    }
    __syncthreads();
    m = red[0];
    __syncthreads();

    float s = 0.0f;
    #pragma unroll
    for (int i = 0; i < 8; ++i) {
        v[i] = exp2a(v[i] - m);
        s += v[i];
    }
    s = warp_sum(s);
    if (lid == 0) red[wid] = s;
    __syncthreads();
    if (wid == 0) {
        float t = (lid < 8) ? red[lid] : 0.0f;
        t = warp_sum(t);
        if (lid == 0) red[0] = t;
    }
    __syncthreads();
    const float inv = 1.0f / red[0];

    __half2 h[4];
    #pragma unroll
    for (int i = 0; i < 4; ++i)
        h[i] = __floats2half2_rn(v[2 * i] * inv, v[2 * i + 1] * inv);
    *(uint4*)(P + rowoff + tid * 8) = *(uint4*)h;
}

// ---------------------------------------------------------------------------
extern "C" void kernel_launch(void* const* d_in, const int* in_sizes, int n_in,
                              void* d_out, int out_size)
{
    const float* q  = (const float*)d_in[0];
    const float* kv = (const float*)d_in[1];
    const float* Wq = (const float*)d_in[2];
    const float* Wk = (const float*)d_in[3];
    const float* Wv = (const float*)d_in[4];
    const float* Wo = (const float*)d_in[5];
    const float* bo = (const float*)d_in[6];
    float* out = (float*)d_out;

    __half *q16, *kv16, *wq16, *wk16, *wv16, *wo16;
    __half *qp16, *kp16, *vpT16, *ctx16, *sc16, *p16;
    cudaGetSymbolAddress((void**)&q16,  g_q16);
    cudaGetSymbolAddress((void**)&kv16, g_kv16);
    cudaGetSymbolAddress((void**)&wq16, g_wq16);
    cudaGetSymbolAddress((void**)&wk16, g_wk16);
    cudaGetSymbolAddress((void**)&wv16, g_wv16);
    cudaGetSymbolAddress((void**)&wo16, g_wo16);
    cudaGetSymbolAddress((void**)&qp16,  g_qp16);
    cudaGetSymbolAddress((void**)&kp16,  g_kp16);
    cudaGetSymbolAddress((void**)&vpT16, g_vpT16);
    cudaGetSymbolAddress((void**)&ctx16, g_ctx16);
    cudaGetSymbolAddress((void**)&sc16,  g_sc16);
    cudaGetSymbolAddress((void**)&p16,   g_p16);

    cudaFuncSetAttribute(gemm_hmma16, cudaFuncAttributeMaxDynamicSharedMemorySize,
                         SMEM_TOTAL);

    const int MT = BATCH * SEQ;        // 8192

    // 0a) inputs -> fp16 (launch 0)
    {
        const long long n0 = (long long)BATCH * SEQ * DQ  / 4;  // q
        const long long n1 = (long long)BATCH * SEQ * DKV / 4;  // kv
        const long long tot = n0 + n1;
        conv2_kernel<<<(int)((tot + 255) / 256), 256>>>(
            (const float4*)q,  (uint2*)q16,  n0, 1.0f,
            (const float4*)kv, (uint2*)kv16, n1, 1.0f);
    }
    // 0b) weights -> fp16; Wq pre-scaled by log2(e)/16 (launch 1)
    {
        const long long n0 = (long long)DQ * DQ  / 4;
        const long long n1 = (long long)DQ * DKV / 4;
        const long long n2 = (long long)DQ * DKV / 4;
        const long long n3 = (long long)DQ * DQ  / 4;
        const long long tot = n0 + n1 + n2 + n3;
        conv4_kernel<<<(int)((tot + 255) / 256), 256>>>(
            (const float4*)Wq, (uint2*)wq16, n0, QK_SCALE,
            (const float4*)Wk, (uint2*)wk16, n1, 1.0f,
            (const float4*)Wv, (uint2*)wv16, n2, 1.0f,
            (const float4*)Wo, (uint2*)wo16, n3, 1.0f);
    }

    // 1) qp16 = q16 @ (Wq*scale)^T          (launch 2)
    gemm_hmma16<<<dim3(DQ / TBN, MT / TBM, 1), NTHREADS, SMEM_TOTAL>>>(
        q16, wq16, nullptr, qp16, DQ, DQ, DQ, DQ, 1,
        0, 0, 0, 0, 0, 0, 1.0f, 1);

    // 2) kp16 = kv16 @ Wk^T                 (launch 3)
    gemm_hmma16<<<dim3(DQ / TBN, MT / TBM, 1), NTHREADS, SMEM_TOTAL>>>(
        kv16, wk16, nullptr, kp16, DKV, DKV, DKV, DQ, 1,
        0, 0, 0, 0, 0, 0, 1.0f, 1);

    // 3) vpT16 = (kv16 @ Wv^T)^T            (launch 4)  stored [b, n(1024), l(2048)]
    gemm_hmma16<<<dim3(DQ / TBN, MT / TBM, 1), NTHREADS, SMEM_TOTAL>>>(
        kv16, wv16, nullptr, vpT16, DKV, DKV, DKV, 0, 1,
        0, 0, 0, 0, 0, 0, 1.0f, 2);

    // 4) sc16[b,h] = qh @ kh^T (log2-domain, fp16 out)  (launch 5 -> ncu target)
    gemm_hmma16<<<dim3(SEQ / TBN, SEQ / TBM, BATCH * NH), NTHREADS, SMEM_TOTAL>>>(
        qp16, kp16, nullptr, sc16, HD, DQ, DQ, SEQ, NH,
        (long long)SEQ * DQ, HD,
        (long long)SEQ * DQ, HD,
        (long long)NH * SEQ * SEQ, (long long)SEQ * SEQ,
        1.0f, 1);

    // 5) softmax (base-2): fp16 scores -> fp16 probs    (launch 6)
    softmax16_kernel<<<dim3(BATCH * NH * SEQ), dim3(256)>>>(sc16, p16);

    // 6) ctx16 = P @ vpT16^T (NT)                       (launch 7)
    gemm_hmma16<<<dim3(HD / TBN, SEQ / TBM, BATCH * NH), NTHREADS, SMEM_TOTAL>>>(
        p16, vpT16, nullptr, ctx16, SEQ, SEQ, SEQ, DQ, NH,
        (long long)NH * SEQ * SEQ, (long long)SEQ * SEQ,
        (long long)DQ * SEQ, (long long)HD * SEQ,
        (long long)SEQ * DQ, HD,
        1.0f, 1);

    // 7) out = ctx16 @ Wo^T + bo  (fp32 out)            (launch 8)
    gemm_hmma16<<<dim3(DQ / TBN, MT / TBM, 1), NTHREADS, SMEM_TOTAL>>>(
        ctx16, wo16, bo, out, DQ, DQ, DQ, DQ, 1,
        0, 0, 0, 0, 0, 0, 1.0f, 0);
}

// round 13
// speedup vs baseline: 1.2407x; 1.0335x over previous
#include <cuda_runtime.h>
#include <cuda_fp16.h>
#include <cstdint>
#include <math.h>

// Problem constants
#define BATCH 4
#define SEQ   2048
#define DQ    1024
#define DKV   768
#define NH    4
#define HD    256

// HMMA GEMM tiling
#define TBM 128
#define TBN 128
#define TBK 32
#define NTHREADS 256
#define ROWB  80
#define ATILE (128 * ROWB)             // 10240
#define STAGEB (2 * ATILE)             // 20480
#define NSTAGE 4
#define SMEM_TOTAL (NSTAGE * STAGEB)   // 81920 B

// NN-mode B tile: 32 k-rows x 128 n-cols fp16, 16B row pad
#define BROWB 272
#define BTILE (32 * BROWB)             // 8704
#define STAGEB_NN (ATILE + BTILE)      // 18944
#define SMEM_NN (NSTAGE * STAGEB_NN)   // 75776 B

#define QK_SCALE 0.09016844005555897f  // log2(e) / 16

// -------- scratch (device globals; no cudaMalloc allowed) -------------------
__device__ __half g_q16 [(long long)BATCH * SEQ * DQ];
__device__ __half g_kv16[(long long)BATCH * SEQ * DKV];
__device__ __half g_wq16[DQ * DQ];
__device__ __half g_wk16[DQ * DKV];
__device__ __half g_wv16[DQ * DKV];
__device__ __half g_wo16[DQ * DQ];
__device__ __half g_qp16 [(long long)BATCH * SEQ * DQ];
__device__ __half g_kp16 [(long long)BATCH * SEQ * DQ];
__device__ __half g_vp16 [(long long)BATCH * SEQ * DQ];       // V normal layout
__device__ __half g_ctx16[(long long)BATCH * SEQ * DQ];
__device__ __half g_sc16 [(long long)BATCH * NH * SEQ * SEQ]; // fp16 scores
__device__ __half g_p16  [(long long)BATCH * NH * SEQ * SEQ]; // fp16 probs

// ---------------------------- helpers ---------------------------------------
__device__ __forceinline__ uint32_t smem_u32(const void* p) {
    uint32_t a;
    asm("{ .reg .u64 t; cvta.to.shared.u64 t, %1; cvt.u32.u64 %0, t; }"
        : "=r"(a) : "l"(p));
    return a;
}

__device__ __forceinline__ void cp16(uint32_t dst, const void* src) {
    asm volatile("cp.async.cg.shared.global [%0], [%1], 16;"
                 :: "r"(dst), "l"(src) : "memory");
}

__device__ __forceinline__ void ldsm4(uint32_t addr, uint32_t& r0, uint32_t& r1,
                                      uint32_t& r2, uint32_t& r3) {
    asm volatile("ldmatrix.sync.aligned.m8n8.x4.shared.b16 {%0,%1,%2,%3}, [%4];"
                 : "=r"(r0), "=r"(r1), "=r"(r2), "=r"(r3) : "r"(addr));
}

__device__ __forceinline__ void ldsm4t(uint32_t addr, uint32_t& r0, uint32_t& r1,
                                       uint32_t& r2, uint32_t& r3) {
    asm volatile("ldmatrix.sync.aligned.m8n8.x4.trans.shared.b16 {%0,%1,%2,%3}, [%4];"
                 : "=r"(r0), "=r"(r1), "=r"(r2), "=r"(r3) : "r"(addr));
}

__device__ __forceinline__ void mma16816(float* c, const uint32_t* a,
                                         const uint32_t* b) {
    asm volatile(
        "mma.sync.aligned.m16n8k16.row.col.f32.f16.f16.f32 "
        "{%0,%1,%2,%3}, {%4,%5,%6,%7}, {%8,%9}, {%0,%1,%2,%3};"
        : "+f"(c[0]), "+f"(c[1]), "+f"(c[2]), "+f"(c[3])
        : "r"(a[0]), "r"(a[1]), "r"(a[2]), "r"(a[3]), "r"(b[0]), "r"(b[1]));
}

__device__ __forceinline__ float exp2a(float x) {
    float r;
    asm("ex2.approx.f32 %0, %1;" : "=f"(r) : "f"(x));
    return r;
}

// ---------------------------------------------------------------------------
// Segmented fp32 -> fp16 conversions
// ---------------------------------------------------------------------------
__global__ void conv2_kernel(const float4* __restrict__ s0, uint2* __restrict__ d0,
                             long long n0, float m0,
                             const float4* __restrict__ s1, uint2* __restrict__ d1,
                             long long n1, float m1)
{
    long long i = (long long)blockIdx.x * blockDim.x + threadIdx.x;
    const float4* s; uint2* d; float m;
    if (i < n0) { s = s0 + i; d = d0 + i; m = m0; }
    else {
        i -= n0;
        if (i >= n1) return;
        s = s1 + i; d = d1 + i; m = m1;
    }
    float4 v = *s;
    __half2 h0 = __floats2half2_rn(v.x * m, v.y * m);
    __half2 h1 = __floats2half2_rn(v.z * m, v.w * m);
    uint2 u;
    u.x = *reinterpret_cast<uint32_t*>(&h0);
    u.y = *reinterpret_cast<uint32_t*>(&h1);
    *d = u;
}

__global__ void conv4_kernel(const float4* __restrict__ s0, uint2* __restrict__ d0,
                             long long n0, float m0,
                             const float4* __restrict__ s1, uint2* __restrict__ d1,
                             long long n1, float m1,
                             const float4* __restrict__ s2, uint2* __restrict__ d2,
                             long long n2, float m2,
                             const float4* __restrict__ s3, uint2* __restrict__ d3,
                             long long n3, float m3)
{
    long long i = (long long)blockIdx.x * blockDim.x + threadIdx.x;
    const float4* s; uint2* d; float m;
    if (i < n0) { s = s0 + i; d = d0 + i; m = m0; }
    else if (i < n0 + n1) { i -= n0; s = s1 + i; d = d1 + i; m = m1; }
    else if (i < n0 + n1 + n2) { i -= n0 + n1; s = s2 + i; d = d2 + i; m = m2; }
    else {
        i -= n0 + n1 + n2;
        if (i >= n3) return;
        s = s3 + i; d = d3 + i; m = m3;
    }
    float4 v = *s;
    __half2 h0 = __floats2half2_rn(v.x * m, v.y * m);
    __half2 h1 = __floats2half2_rn(v.z * m, v.w * m);
    uint2 u;
    u.x = *reinterpret_cast<uint32_t*>(&h0);
    u.y = *reinterpret_cast<uint32_t*>(&h1);
    *d = u;
}

// ---------------------------------------------------------------------------
// HMMA fp16 NT GEMM, cp.async 4-stage, 2 CTAs/SM.
//   C[m,n] = alpha * sum_k A[m,k]*B[n,k]  (+ bias[n] if mode 0)
// outMode: 0 = fp32 C (+bias), 1 = fp16 C
// ---------------------------------------------------------------------------
__global__ __launch_bounds__(NTHREADS, 2)
void gemm_hmma16(const __half* __restrict__ A, const __half* __restrict__ B,
                 const float* __restrict__ bias, void* __restrict__ Cv,
                 int K, int lda, int ldb, int ldc, int nh,
                 long long sAb, long long sAh, long long sBb, long long sBh,
                 long long sCb, long long sCh, float alpha, int outMode)
{
    extern __shared__ __align__(16) char sm[];
    const uint32_t smbase = smem_u32(sm);

    const int tid = threadIdx.x;
    const int lane = tid & 31, wid = tid >> 5;
    const int wm = wid & 3, wn = wid >> 2;

    const int z = blockIdx.z, bz = z / nh, hz = z - bz * nh;
    A += bz * sAb + hz * sAh;
    B += bz * sBb + hz * sBh;
    const int bm = blockIdx.y * TBM, bn = blockIdx.x * TBN;

    const int srow = tid >> 2;
    const int sc   = tid & 3;
    const __half* gA = A + (long long)(bm + srow) * lda + sc * 8;
    const __half* gB = B + (long long)(bn + srow) * ldb + sc * 8;
    const uint32_t stsA = smbase + (uint32_t)srow * ROWB + sc * 16;
    const uint32_t stsB = stsA + ATILE;
    const long long a64 = 64LL * lda, b64 = 64LL * ldb;

    uint32_t a_addr[2], b_addr[4];
    {
        const int ar = wm * 32 + (lane & 15);
        const int ac = lane >> 4;
        #pragma unroll
        for (int t = 0; t < 2; ++t)
            a_addr[t] = smbase + (uint32_t)(ar + t * 16) * ROWB + ac * 16;
        const int br = wn * 64 + (lane & 7) + ((lane >> 4) << 3);
        const int bc = (lane >> 3) & 1;
        #pragma unroll
        for (int u = 0; u < 4; ++u)
            b_addr[u] = smbase + ATILE + (uint32_t)(br + u * 16) * ROWB + bc * 16;
    }

    float c[2][8][4];
    #pragma unroll
    for (int t = 0; t < 2; ++t)
        #pragma unroll
        for (int j = 0; j < 8; ++j)
            #pragma unroll
            for (int r = 0; r < 4; ++r)
                c[t][j][r] = 0.0f;

    const int KT = K / TBK;

    #pragma unroll
    for (int p = 0; p < NSTAGE - 1; ++p) {
        const uint32_t so = (uint32_t)p * STAGEB;
        const int kp = p * TBK;
        cp16(stsA + so, gA + kp);
        cp16(stsA + so + 64 * ROWB, gA + kp + a64);
        cp16(stsB + so, gB + kp);
        cp16(stsB + so + 64 * ROWB, gB + kp + b64);
        asm volatile("cp.async.commit_group;" ::: "memory");
    }

    for (int kt = 0; kt < KT; ++kt) {
        asm volatile("cp.async.wait_group %0;" :: "n"(NSTAGE - 2) : "memory");
        __syncthreads();

        const int ns = kt + NSTAGE - 1;
        if (ns < KT) {
            const uint32_t so = (uint32_t)(ns & (NSTAGE - 1)) * STAGEB;
            const int kp = ns * TBK;
            cp16(stsA + so, gA + kp);
            cp16(stsA + so + 64 * ROWB, gA + kp + a64);
            cp16(stsB + so, gB + kp);
            cp16(stsB + so + 64 * ROWB, gB + kp + b64);
        }
        asm volatile("cp.async.commit_group;" ::: "memory");

        const uint32_t soff = (uint32_t)(kt & (NSTAGE - 1)) * STAGEB;
        #pragma unroll
        for (int s = 0; s < 2; ++s) {
            uint32_t af[2][4], bf[4][4];
            #pragma unroll
            for (int t = 0; t < 2; ++t)
                ldsm4(a_addr[t] + soff + s * 32,
                      af[t][0], af[t][1], af[t][2], af[t][3]);
            #pragma unroll
            for (int u = 0; u < 4; ++u)
                ldsm4(b_addr[u] + soff + s * 32,
                      bf[u][0], bf[u][1], bf[u][2], bf[u][3]);
            #pragma unroll
            for (int t = 0; t < 2; ++t)
                #pragma unroll
                for (int j = 0; j < 8; ++j)
                    mma16816(c[t][j], af[t], &bf[j >> 1][(j & 1) * 2]);
        }
    }

    #pragma unroll
    for (int t = 0; t < 2; ++t) {
        const int m0 = bm + wm * 32 + t * 16 + (lane >> 2);
        #pragma unroll
        for (int j = 0; j < 8; ++j) {
            const int n0 = bn + wn * 64 + j * 8 + (lane & 3) * 2;
            float v0 = c[t][j][0] * alpha;
            float v1 = c[t][j][1] * alpha;
            float v2 = c[t][j][2] * alpha;
            float v3 = c[t][j][3] * alpha;
            if (outMode == 0) {
                float* C = (float*)Cv + bz * sCb + hz * sCh;
                if (bias) {
                    const float b0 = bias[n0], b1 = bias[n0 + 1];
                    v0 += b0; v1 += b1; v2 += b0; v3 += b1;
                }
                *(float2*)(C + (long long)m0 * ldc + n0) = make_float2(v0, v1);
                *(float2*)(C + (long long)(m0 + 8) * ldc + n0) = make_float2(v2, v3);
            } else {
                __half* C = (__half*)Cv + bz * sCb + hz * sCh;
                __half2 lo = __floats2half2_rn(v0, v1);
                __half2 hi = __floats2half2_rn(v2, v3);
                *(__half2*)(C + (long long)m0 * ldc + n0) = lo;
                *(__half2*)(C + (long long)(m0 + 8) * ldc + n0) = hi;
            }
        }
    }
}

// ---------------------------------------------------------------------------
// HMMA fp16 NN GEMM: C[m,n] = sum_k A[m,k] * B[k,n], fp16 out.
// A K-contig; B natural [K, N] rows (ldb). B frags via ldmatrix.trans.
// Used for PV: A = probs, B = vp16 (keys x 1024, head offset via sBh).
// ---------------------------------------------------------------------------
__global__ __launch_bounds__(NTHREADS, 2)
void gemm_hmma16_nn(const __half* __restrict__ A, const __half* __restrict__ B,
                    __half* __restrict__ C,
                    int K, int lda, int ldb, int ldc, int nh,
                    long long sAb, long long sAh, long long sBb, long long sBh,
                    long long sCb, long long sCh)
{
    extern __shared__ __align__(16) char sm[];
    const uint32_t smbase = smem_u32(sm);

    const int tid = threadIdx.x;
    const int lane = tid & 31, wid = tid >> 5;
    const int wm = wid & 3, wn = wid >> 2;

    const int z = blockIdx.z, bz = z / nh, hz = z - bz * nh;
    A += bz * sAb + hz * sAh;
    B += bz * sBb + hz * sBh;
    C += bz * sCb + hz * sCh;
    const int bm = blockIdx.y * TBM, bn = blockIdx.x * TBN;

    // A staging: 2 threads/row (srow 0..63 + 64), 16B chunks
    const int srow = tid >> 2;
    const int sc   = tid & 3;
    const __half* gA = A + (long long)(bm + srow) * lda + sc * 8;
    const uint32_t stsA = smbase + (uint32_t)srow * ROWB + sc * 16;
    const long long a64 = 64LL * lda;

    // B staging: 32 k-rows x 16 chunks = 512 slots; thread -> slots tid, tid+256
    const int br0 = tid >> 4, bc0 = tid & 15;        // slot tid
    const int br1 = (tid + 256) >> 4, bc1 = tid & 15; // slot tid+256 (same chunk idx)
    const __half* gB0 = B + (long long)br0 * ldb + bn + bc0 * 8;
    const __half* gB1 = B + (long long)br1 * ldb + bn + bc1 * 8;
    const uint32_t stsB0 = smbase + ATILE + (uint32_t)br0 * BROWB + bc0 * 16;
    const uint32_t stsB1 = smbase + ATILE + (uint32_t)br1 * BROWB + bc1 * 16;

    uint32_t a_addr[2], b_addr[4];
    {
        const int ar = wm * 32 + (lane & 15);
        const int ac = lane >> 4;
        #pragma unroll
        for (int t = 0; t < 2; ++t)
            a_addr[t] = smbase + (uint32_t)(ar + t * 16) * ROWB + ac * 16;
        // B trans frags: 16 k-rows (lane&15), 16 n-cols per group; hi lanes +16B
        #pragma unroll
        for (int u = 0; u < 4; ++u)
            b_addr[u] = smbase + ATILE + (uint32_t)(lane & 15) * BROWB
                        + (uint32_t)(wn * 64 + u * 16) * 2 + ((lane >> 4) << 4);
    }

    float c[2][8][4];
    #pragma unroll
    for (int t = 0; t < 2; ++t)
        #pragma unroll
        for (int j = 0; j < 8; ++j)
            #pragma unroll
            for (int r = 0; r < 4; ++r)
                c[t][j][r] = 0.0f;

    const int KT = K / TBK;

    #pragma unroll
    for (int p = 0; p < NSTAGE - 1; ++p) {
        const uint32_t so = (uint32_t)p * STAGEB_NN;
        const int kp = p * TBK;
        cp16(stsA + so, gA + kp);
        cp16(stsA + so + 64 * ROWB, gA + kp + a64);
        cp16(stsB0 + so, gB0 + (long long)kp * ldb);
        cp16(stsB1 + so, gB1 + (long long)kp * ldb);
        asm volatile("cp.async.commit_group;" ::: "memory");
    }

    for (int kt = 0; kt < KT; ++kt) {
        asm volatile("cp.async.wait_group %0;" :: "n"(NSTAGE - 2) : "memory");
        __syncthreads();

        const int ns = kt + NSTAGE - 1;
        if (ns < KT) {
            const uint32_t so = (uint32_t)(ns & (NSTAGE - 1)) * STAGEB_NN;
            const int kp = ns * TBK;
            cp16(stsA + so, gA + kp);
            cp16(stsA + so + 64 * ROWB, gA + kp + a64);
            cp16(stsB0 + so, gB0 + (long long)kp * ldb);
            cp16(stsB1 + so, gB1 + (long long)kp * ldb);
        }
        asm volatile("cp.async.commit_group;" ::: "memory");

        const uint32_t soff = (uint32_t)(kt & (NSTAGE - 1)) * STAGEB_NN;
        #pragma unroll
        for (int s = 0; s < 2; ++s) {
            uint32_t af[2][4], bf[4][4];
            #pragma unroll
            for (int t = 0; t < 2; ++t)
                ldsm4(a_addr[t] + soff + s * 32,
                      af[t][0], af[t][1], af[t][2], af[t][3]);
            #pragma unroll
            for (int u = 0; u < 4; ++u)
                ldsm4t(b_addr[u] + soff + (uint32_t)s * 16 * BROWB,
                       bf[u][0], bf[u][1], bf[u][2], bf[u][3]);
            #pragma unroll
            for (int t = 0; t < 2; ++t)
                #pragma unroll
                for (int u = 0; u < 4; ++u) {
                    mma16816(c[t][2 * u],     af[t], &bf[u][0]);
                    mma16816(c[t][2 * u + 1], af[t], &bf[u][2]);
                }
        }
    }

    #pragma unroll
    for (int t = 0; t < 2; ++t) {
        const int m0 = bm + wm * 32 + t * 16 + (lane >> 2);
        #pragma unroll
        for (int j = 0; j < 8; ++j) {
            const int n0 = bn + wn * 64 + j * 8 + (lane & 3) * 2;
            __half2 lo = __floats2half2_rn(c[t][j][0], c[t][j][1]);
            __half2 hi = __floats2half2_rn(c[t][j][2], c[t][j][3]);
            *(__half2*)(C + (long long)m0 * ldc + n0) = lo;
            *(__half2*)(C + (long long)(m0 + 8) * ldc + n0) = hi;
        }
    }
}

// ---------------------------------------------------------------------------
// Row softmax in base-2: fp16 scores -> fp16 probs. 2048 cols, 256 threads.
// ---------------------------------------------------------------------------
__device__ __forceinline__ float warp_max(float v) {
    #pragma unroll
    for (int o = 16; o > 0; o >>= 1) v = fmaxf(v, __shfl_xor_sync(0xffffffffu, v, o));
    return v;
}
__device__ __forceinline__ float warp_sum(float v) {
    #pragma unroll
    for (int o = 16; o > 0; o >>= 1) v += __shfl_xor_sync(0xffffffffu, v, o);
    return v;
}

__global__ __launch_bounds__(256)
void softmax16_kernel(const __half* __restrict__ S, __half* __restrict__ P)
{
    const long long rowoff = (long long)blockIdx.x * SEQ;
    const int tid = threadIdx.x;
    const int wid = tid >> 5, lid = tid & 31;
    __shared__ float red[8];

    uint4 raw = *(const uint4*)(S + rowoff + tid * 8);
    const __half2* hp = (const __half2*)&raw;
    float v[8];
    #pragma unroll
    for (int i = 0; i < 4; ++i) {
        float2 f = __half22float2(hp[i]);
        v[2 * i] = f.x;
        v[2 * i + 1] = f.y;
    }

    float m = -1e30f;
    #pragma unroll
    for (int i = 0; i < 8; ++i) m = fmaxf(m, v[i]);
    m = warp_max(m);
    if (lid == 0) red[wid] = m;
    __syncthreads();
    if (wid == 0) {
        float t = (lid < 8) ? red[lid] : -1e30f;
        t = warp_max(t);
        if (lid == 0) red[0] = t;
    }
    __syncthreads();
    m = red[0];
    __syncthreads();

    float s = 0.0f;
    #pragma unroll
    for (int i = 0; i < 8; ++i) {
        v[i] = exp2a(v[i] - m);
        s += v[i];
    }
    s = warp_sum(s);
    if (lid == 0) red[wid] = s;
    __syncthreads();
    if (wid == 0) {
        float t = (lid < 8) ? red[lid] : 0.0f;
        t = warp_sum(t);
        if (lid == 0) red[0] = t;
    }
    __syncthreads();
    const float inv = 1.0f / red[0];

    __half2 h[4];
    #pragma unroll
    for (int i = 0; i < 4; ++i)
        h[i] = __floats2half2_rn(v[2 * i] * inv, v[2 * i + 1] * inv);
    *(uint4*)(P + rowoff + tid * 8) = *(uint4*)h;
}

// ---------------------------------------------------------------------------
extern "C" void kernel_launch(void* const* d_in, const int* in_sizes, int n_in,
                              void* d_out, int out_size)
{
    const float* q  = (const float*)d_in[0];
    const float* kv = (const float*)d_in[1];
    const float* Wq = (const float*)d_in[2];
    const float* Wk = (const float*)d_in[3];
    const float* Wv = (const float*)d_in[4];
    const float* Wo = (const float*)d_in[5];
    const float* bo = (const float*)d_in[6];
    float* out = (float*)d_out;

    __half *q16, *kv16, *wq16, *wk16, *wv16, *wo16;
    __half *qp16, *kp16, *vp16, *ctx16, *sc16, *p16;
    cudaGetSymbolAddress((void**)&q16,  g_q16);
    cudaGetSymbolAddress((void**)&kv16, g_kv16);
    cudaGetSymbolAddress((void**)&wq16, g_wq16);
    cudaGetSymbolAddress((void**)&wk16, g_wk16);
    cudaGetSymbolAddress((void**)&wv16, g_wv16);
    cudaGetSymbolAddress((void**)&wo16, g_wo16);
    cudaGetSymbolAddress((void**)&qp16,  g_qp16);
    cudaGetSymbolAddress((void**)&kp16,  g_kp16);
    cudaGetSymbolAddress((void**)&vp16,  g_vp16);
    cudaGetSymbolAddress((void**)&ctx16, g_ctx16);
    cudaGetSymbolAddress((void**)&sc16,  g_sc16);
    cudaGetSymbolAddress((void**)&p16,   g_p16);

    cudaFuncSetAttribute(gemm_hmma16, cudaFuncAttributeMaxDynamicSharedMemorySize,
                         SMEM_TOTAL);
    cudaFuncSetAttribute(gemm_hmma16_nn, cudaFuncAttributeMaxDynamicSharedMemorySize,
                         SMEM_NN);

    const int MT = BATCH * SEQ;        // 8192

    // 0a) inputs -> fp16 (launch 0)
    {
        const long long n0 = (long long)BATCH * SEQ * DQ  / 4;
        const long long n1 = (long long)BATCH * SEQ * DKV / 4;
        const long long tot = n0 + n1;
        conv2_kernel<<<(int)((tot + 255) / 256), 256>>>(
            (const float4*)q,  (uint2*)q16,  n0, 1.0f,
            (const float4*)kv, (uint2*)kv16, n1, 1.0f);
    }
    // 0b) weights -> fp16; Wq pre-scaled by log2(e)/16 (launch 1)
    {
        const long long n0 = (long long)DQ * DQ  / 4;
        const long long n1 = (long long)DQ * DKV / 4;
        const long long n2 = (long long)DQ * DKV / 4;
        const long long n3 = (long long)DQ * DQ  / 4;
        const long long tot = n0 + n1 + n2 + n3;
        conv4_kernel<<<(int)((tot + 255) / 256), 256>>>(
            (const float4*)Wq, (uint2*)wq16, n0, QK_SCALE,
            (const float4*)Wk, (uint2*)wk16, n1, 1.0f,
            (const float4*)Wv, (uint2*)wv16, n2, 1.0f,
            (const float4*)Wo, (uint2*)wo16, n3, 1.0f);
    }

    // 1) qp16 = q16 @ (Wq*scale)^T          (launch 2)
    gemm_hmma16<<<dim3(DQ / TBN, MT / TBM, 1), NTHREADS, SMEM_TOTAL>>>(
        q16, wq16, nullptr, qp16, DQ, DQ, DQ, DQ, 1,
        0, 0, 0, 0, 0, 0, 1.0f, 1);

    // 2) kp16 = kv16 @ Wk^T                 (launch 3)
    gemm_hmma16<<<dim3(DQ / TBN, MT / TBM, 1), NTHREADS, SMEM_TOTAL>>>(
        kv16, wk16, nullptr, kp16, DKV, DKV, DKV, DQ, 1,
        0, 0, 0, 0, 0, 0, 1.0f, 1);

    // 3) vp16 = kv16 @ Wv^T (normal layout) (launch 4)
    gemm_hmma16<<<dim3(DQ / TBN, MT / TBM, 1), NTHREADS, SMEM_TOTAL>>>(
        kv16, wv16, nullptr, vp16, DKV, DKV, DKV, DQ, 1,
        0, 0, 0, 0, 0, 0, 1.0f, 1);

    // 4) sc16[b,h] = qh @ kh^T (log2-domain) (launch 5 -> ncu target)
    gemm_hmma16<<<dim3(SEQ / TBN, SEQ / TBM, BATCH * NH), NTHREADS, SMEM_TOTAL>>>(
        qp16, kp16, nullptr, sc16, HD, DQ, DQ, SEQ, NH,
        (long long)SEQ * DQ, HD,
        (long long)SEQ * DQ, HD,
        (long long)NH * SEQ * SEQ, (long long)SEQ * SEQ,
        1.0f, 1);

    // 5) softmax (base-2)                   (launch 6)
    softmax16_kernel<<<dim3(BATCH * NH * SEQ), dim3(256)>>>(sc16, p16);

    // 6) ctx16 = P @ vp16 (NN, B natural)   (launch 7)
    gemm_hmma16_nn<<<dim3(HD / TBN, SEQ / TBM, BATCH * NH), NTHREADS, SMEM_NN>>>(
        p16, vp16, ctx16, SEQ, SEQ, DQ, DQ, NH,
        (long long)NH * SEQ * SEQ, (long long)SEQ * SEQ,
        (long long)SEQ * DQ, HD,
        (long long)SEQ * DQ, HD);

    // 7) out = ctx16 @ Wo^T + bo  (fp32 out) (launch 8)
    gemm_hmma16<<<dim3(DQ / TBN, MT / TBM, 1), NTHREADS, SMEM_TOTAL>>>(
        ctx16, wo16, bo, out, DQ, DQ, DQ, DQ, 1,
        0, 0, 0, 0, 0, 0, 1.0f, 0);
}